// round 14
// baseline (speedup 1.0000x reference)
#include <cuda_runtime.h>
#include <cstdint>

// Problem constants
#define BB 4
#define N1 8192
#define N2 2048
#define INP 512
#define OUTP 256
#define M1 (BB * N1)   // 32768
#define M2 (BB * N2)   // 8192

// Device scratch
__device__ float g_y1[M1 * OUTP];     // x1@W1+b1  (32 MB)
__device__ float g_y2[M2 * OUTP];     // x2@W2+b2  (8 MB)
__device__ float g_Wt1[OUTP * OUTP];  // W1^T  [N,K]
__device__ float g_Wt2[OUTP * INP];   // W2^T  [N,K]
__device__ float g_stats1[2 * OUTP];
__device__ float g_stats2[2 * OUTP];
__device__ float g_ab1[2 * OUTP];
__device__ float g_ab2[2 * OUTP];
__device__ int   g_idx[BB * N1 * 3];
__device__ float g_w[BB * N1 * 3];

// smem row stride for tf32 tiles: 36 words = 144 bytes.
#define SW 36
#define STAGE_BYTES (2 * 128 * SW * 4)      // A + B per stage = 36864
#define B_OFF_BYTES (128 * SW * 4)          // 18432
#define GEMM_SMEM   (2 * STAGE_BYTES)       // 73728

// ---------------------------------------------------------------------------
__device__ __forceinline__ uint32_t smem_u32(const void* p) {
    uint32_t a;
    asm("{ .reg .u64 t; cvta.to.shared.u64 t, %1; cvt.u32.u64 %0, t; }"
        : "=r"(a) : "l"(p));
    return a;
}

__device__ __forceinline__ void ldmx4(uint32_t addr, uint32_t* r) {
    asm volatile("ldmatrix.sync.aligned.m8n8.x4.shared.b16 {%0,%1,%2,%3}, [%4];"
                 : "=r"(r[0]), "=r"(r[1]), "=r"(r[2]), "=r"(r[3]) : "r"(addr));
}

// m16n8k8 tf32 MMA, fp32 accumulate
__device__ __forceinline__ void mma_tf32(float* c, const uint32_t* a,
                                         const uint32_t* b) {
    asm volatile(
        "mma.sync.aligned.m16n8k8.row.col.f32.tf32.tf32.f32 "
        "{%0,%1,%2,%3}, {%4,%5,%6,%7}, {%8,%9}, {%0,%1,%2,%3};"
        : "+f"(c[0]), "+f"(c[1]), "+f"(c[2]), "+f"(c[3])
        : "r"(a[0]), "r"(a[1]), "r"(a[2]), "r"(a[3]), "r"(b[0]), "r"(b[1]));
}

__device__ __forceinline__ void cpasync16(uint32_t d, const void* s) {
    asm volatile("cp.async.cg.shared.global [%0], [%1], 16;"
                 :: "r"(d), "l"(s) : "memory");
}
#define CP_COMMIT() asm volatile("cp.async.commit_group;" ::: "memory")
#define CP_WAIT1()  asm volatile("cp.async.wait_group 1;" ::: "memory")

// ---------------------------------------------------------------------------
__global__ void zero_stats_kernel() {
    int t = threadIdx.x;
    if (t < 2 * OUTP) { g_stats1[t] = 0.f; g_stats2[t] = 0.f; }
}

// Tiled transpose: dst[C][R] = src[R][C]^T. block (32,8), grid (C/32, R/32)
__global__ __launch_bounds__(256) void transpose_kernel(
    const float* __restrict__ src, float* __restrict__ dst, int R, int C)
{
    __shared__ float t[32][33];
    int bx = blockIdx.x * 32, by = blockIdx.y * 32;
    int x = bx + threadIdx.x;
    #pragma unroll
    for (int i = 0; i < 32; i += 8)
        t[threadIdx.y + i][threadIdx.x] = src[(size_t)(by + threadIdx.y + i) * C + x];
    __syncthreads();
    int x2 = by + threadIdx.x;
    #pragma unroll
    for (int i = 0; i < 32; i += 8)
        dst[(size_t)(bx + threadIdx.y + i) * R + x2] = t[threadIdx.x][threadIdx.y + i];
}

// ---------------------------------------------------------------------------
// TF32 HMMA GEMM, cp.async double-buffered (R12 winner, unchanged).
template<int K>
__global__ __launch_bounds__(256) void gemm_tf32_pipe_kernel(
    const float* __restrict__ A, const float* __restrict__ Wt,
    const float* __restrict__ bias, float* __restrict__ C)
{
    extern __shared__ uint32_t smem[];
    const uint32_t base_u = smem_u32(smem);
    constexpr int NCH = K / 32;

    const int tid = threadIdx.x;
    const int wid = tid >> 5;
    const int lane = tid & 31;
    const int gid = lane >> 2;
    const int tig = lane & 3;

    const int rowBase = blockIdx.y * 128;
    const int colBase = blockIdx.x * 128;
    const int m0 = (wid & 1) * 64;
    const int n0 = (wid >> 1) * 32;

    const int lrow = ((lane >> 3) & 1) * 8 + (lane & 7);
    const int lc16 = (lane >> 4) * 16;
    const uint32_t aLane = (uint32_t)(m0 + lrow) * 144 + lc16;
    const uint32_t bLane = (uint32_t)(n0 + lrow) * 144 + lc16 + B_OFF_BYTES;

    const int ldRow = tid >> 3;
    const int ldC = tid & 7;

    float acc[4][4][4];
    #pragma unroll
    for (int mt = 0; mt < 4; mt++)
        #pragma unroll
        for (int nt = 0; nt < 4; nt++)
            #pragma unroll
            for (int e = 0; e < 4; e++) acc[mt][nt][e] = 0.f;

    auto issue_stage = [&](int slot, int k0) {
        const uint32_t st = base_u + slot * STAGE_BYTES;
        #pragma unroll
        for (int l = 0; l < 4; l++) {
            int r = ldRow + l * 32;
            uint32_t d = st + (uint32_t)r * 144 + ldC * 16;
            cpasync16(d, A + (size_t)(rowBase + r) * K + k0 + ldC * 4);
            cpasync16(d + B_OFF_BYTES, Wt + (size_t)(colBase + r) * K + k0 + ldC * 4);
        }
        CP_COMMIT();
    };

    issue_stage(0, 0);
    issue_stage(1, 32);

    for (int c = 0; c < NCH; c++) {
        CP_WAIT1();
        __syncthreads();
        const uint32_t st = base_u + (c & 1) * STAGE_BYTES;
        const uint32_t aBase = st + aLane;
        const uint32_t bBase = st + bLane;

        #pragma unroll
        for (int kt = 0; kt < 4; kt++) {
            uint32_t b[4][2];
            #pragma unroll
            for (int np = 0; np < 2; np++) {
                uint32_t r4[4];
                ldmx4(bBase + np * (16 * 144) + kt * 32, r4);
                b[np * 2][0]     = r4[0];
                b[np * 2 + 1][0] = r4[1];
                b[np * 2][1]     = r4[2];
                b[np * 2 + 1][1] = r4[3];
            }
            #pragma unroll
            for (int mt = 0; mt < 4; mt++) {
                uint32_t a[4];
                ldmx4(aBase + mt * (16 * 144) + kt * 32, a);
                #pragma unroll
                for (int nt = 0; nt < 4; nt++)
                    mma_tf32(acc[mt][nt], a, b[nt]);
            }
        }
        __syncthreads();
        if (c + 2 < NCH) issue_stage(c & 1, (c + 2) * 32);
        else CP_COMMIT();
    }

    #pragma unroll
    for (int nt = 0; nt < 4; nt++) {
        const int cg = colBase + n0 + nt * 8 + tig * 2;
        float2 bv = *(const float2*)(bias + cg);
        #pragma unroll
        for (int mt = 0; mt < 4; mt++) {
            int rg0 = rowBase + m0 + mt * 16 + gid;
            float2 v0 = make_float2(acc[mt][nt][0] + bv.x, acc[mt][nt][1] + bv.y);
            float2 v1 = make_float2(acc[mt][nt][2] + bv.x, acc[mt][nt][3] + bv.y);
            *(float2*)(C + (size_t)rg0 * OUTP + cg) = v0;
            *(float2*)(C + (size_t)(rg0 + 8) * OUTP + cg) = v1;
        }
    }
}

// ---------------------------------------------------------------------------
__global__ __launch_bounds__(256) void stats_kernel(
    const float* __restrict__ y, int rows, float* __restrict__ stats)
{
    int c = threadIdx.x;
    float s = 0.f, q = 0.f;
    for (int r = blockIdx.x; r < rows; r += gridDim.x) {
        float v = y[(size_t)r * OUTP + c];
        s += v;
        q = fmaf(v, v, q);
    }
    atomicAdd(&stats[c], s);
    atomicAdd(&stats[OUTP + c], q);
}

__global__ void finalize_kernel(const float* __restrict__ stats,
                                const float* __restrict__ gamma,
                                const float* __restrict__ beta,
                                float inv_count, float* __restrict__ ab)
{
    int c = threadIdx.x;
    float mean = stats[c] * inv_count;
    float var  = stats[OUTP + c] * inv_count - mean * mean;
    float scale = gamma[c] * rsqrtf(var + 1e-5f);
    ab[c]        = scale;
    ab[OUTP + c] = beta[c] - mean * scale;
}

// ---------------------------------------------------------------------------
// 3-NN (proven scan)
__global__ __launch_bounds__(256) void knn_kernel(
    const float* __restrict__ p1, const float* __restrict__ p2)
{
    __shared__ float4 sp[N2];
    const int b     = blockIdx.x >> 5;
    const int chunk = blockIdx.x & 31;

    const float* P2 = p2 + (size_t)b * N2 * 3;
    for (int i = threadIdx.x; i < N2; i += 256) {
        float x = P2[i * 3 + 0], y = P2[i * 3 + 1], z = P2[i * 3 + 2];
        sp[i] = make_float4(x, y, z, fmaf(x, x, fmaf(y, y, z * z)));
    }
    __syncthreads();

    const int n = chunk * 256 + threadIdx.x;
    const float* P1 = p1 + ((size_t)b * N1 + n) * 3;
    const float px = P1[0], py = P1[1], pz = P1[2];
    const float s1 = fmaf(px, px, fmaf(py, py, pz * pz));

    float d0 = 1e30f, d1 = 1e30f, d2 = 1e30f;
    int   i0 = 0,     i1 = 0,     i2 = 0;

    #pragma unroll 4
    for (int j = 0; j < N2; j++) {
        float4 qq = sp[j];
        float dot = fmaf(px, qq.x, fmaf(py, qq.y, pz * qq.z));
        float d = (s1 + qq.w) - 2.f * dot;
        if (d < d2) {
            if (d < d1) {
                d2 = d1; i2 = i1;
                if (d < d0) { d1 = d0; i1 = i0; d0 = d; i0 = j; }
                else        { d1 = d;  i1 = j; }
            } else { d2 = d; i2 = j; }
        }
    }

    float r0 = 1.f / (d0 + 1e-8f);
    float r1 = 1.f / (d1 + 1e-8f);
    float r2 = 1.f / (d2 + 1e-8f);
    float rs = 1.f / (r0 + r1 + r2);

    size_t o = ((size_t)b * N1 + n) * 3;
    g_idx[o + 0] = b * N2 + i0;
    g_idx[o + 1] = b * N2 + i1;
    g_idx[o + 2] = b * N2 + i2;
    g_w[o + 0] = r0 * rs;
    g_w[o + 1] = r1 * rs;
    g_w[o + 2] = r2 * rs;
}

// ---------------------------------------------------------------------------
__global__ __launch_bounds__(256) void out_kernel(float* __restrict__ out)
{
    const int r = blockIdx.x;
    const int c = threadIdx.x;

    const float a1 = g_ab1[c], s1 = g_ab1[OUTP + c];
    const float a2 = g_ab2[c], s2 = g_ab2[OUTP + c];

    const size_t o3 = (size_t)r * 3;
    const int   j0 = g_idx[o3 + 0], j1 = g_idx[o3 + 1], j2 = g_idx[o3 + 2];
    const float w0 = g_w[o3 + 0],   w1 = g_w[o3 + 1],   w2 = g_w[o3 + 2];

    float v1 = fmaxf(fmaf(g_y1[(size_t)r * OUTP + c], a1, s1), 0.f);
    float h0 = fmaxf(fmaf(g_y2[(size_t)j0 * OUTP + c], a2, s2), 0.f);
    float h1 = fmaxf(fmaf(g_y2[(size_t)j1 * OUTP + c], a2, s2), 0.f);
    float h2 = fmaxf(fmaf(g_y2[(size_t)j2 * OUTP + c], a2, s2), 0.f);

    out[(size_t)r * OUTP + c] = v1 + fmaf(w0, h0, fmaf(w1, h1, w2 * h2));
}

// ---------------------------------------------------------------------------
extern "C" void kernel_launch(void* const* d_in, const int* in_sizes, int n_in,
                              void* d_out, int out_size)
{
    const float* p1     = (const float*)d_in[0];
    const float* x1     = (const float*)d_in[1];
    const float* p2     = (const float*)d_in[2];
    const float* x2     = (const float*)d_in[3];
    const float* W1     = (const float*)d_in[4];
    const float* b1     = (const float*)d_in[5];
    const float* gamma1 = (const float*)d_in[6];
    const float* beta1  = (const float*)d_in[7];
    const float* W2     = (const float*)d_in[8];
    const float* b2     = (const float*)d_in[9];
    const float* gamma2 = (const float*)d_in[10];
    const float* beta2  = (const float*)d_in[11];
    float* out = (float*)d_out;

    float *y1, *y2, *st1, *st2, *ab1, *ab2, *wt1, *wt2;
    cudaGetSymbolAddress((void**)&y1,  g_y1);
    cudaGetSymbolAddress((void**)&y2,  g_y2);
    cudaGetSymbolAddress((void**)&st1, g_stats1);
    cudaGetSymbolAddress((void**)&st2, g_stats2);
    cudaGetSymbolAddress((void**)&ab1, g_ab1);
    cudaGetSymbolAddress((void**)&ab2, g_ab2);
    cudaGetSymbolAddress((void**)&wt1, g_Wt1);
    cudaGetSymbolAddress((void**)&wt2, g_Wt2);

    cudaFuncSetAttribute(gemm_tf32_pipe_kernel<INP>,
                         cudaFuncAttributeMaxDynamicSharedMemorySize, GEMM_SMEM);
    cudaFuncSetAttribute(gemm_tf32_pipe_kernel<OUTP>,
                         cudaFuncAttributeMaxDynamicSharedMemorySize, GEMM_SMEM);

    // Fork/join multi-stream DAG (capture-legal: forked streams join the
    // capture via event waits and are joined back before out_kernel).
    cudaStream_t s1, s2;
    cudaStreamCreateWithFlags(&s1, cudaStreamNonBlocking);
    cudaStreamCreateWithFlags(&s2, cudaStreamNonBlocking);
    cudaEvent_t evFork, evJ1, evJ2;
    cudaEventCreateWithFlags(&evFork, cudaEventDisableTiming);
    cudaEventCreateWithFlags(&evJ1, cudaEventDisableTiming);
    cudaEventCreateWithFlags(&evJ2, cudaEventDisableTiming);

    zero_stats_kernel<<<1, 512>>>();
    cudaEventRecord(evFork, 0);
    cudaStreamWaitEvent(s1, evFork, 0);
    cudaStreamWaitEvent(s2, evFork, 0);

    // Branch s1: GEMM2 chain
    transpose_kernel<<<dim3(OUTP / 32, INP / 32), dim3(32, 8), 0, s1>>>(W2, wt2, INP, OUTP);
    gemm_tf32_pipe_kernel<INP><<<dim3(2, M2 / 128), 256, GEMM_SMEM, s1>>>(x2, wt2, b2, y2);
    stats_kernel<<<512, 256, 0, s1>>>(y2, M2, st2);
    finalize_kernel<<<1, 256, 0, s1>>>(st2, gamma2, beta2, 1.f / (float)M2, ab2);

    // Branch s2: knn
    knn_kernel<<<BB * (N1 / 256), 256, 0, s2>>>(p1, p2);

    // Main branch: GEMM1 chain
    transpose_kernel<<<dim3(OUTP / 32, OUTP / 32), dim3(32, 8)>>>(W1, wt1, OUTP, OUTP);
    gemm_tf32_pipe_kernel<OUTP><<<dim3(2, M1 / 128), 256, GEMM_SMEM>>>(x1, wt1, b1, y1);
    stats_kernel<<<2048, 256>>>(y1, M1, st1);
    finalize_kernel<<<1, 256>>>(st1, gamma1, beta1, 1.f / (float)M1, ab1);

    // Join
    cudaEventRecord(evJ1, s1);
    cudaEventRecord(evJ2, s2);
    cudaStreamWaitEvent(0, evJ1, 0);
    cudaStreamWaitEvent(0, evJ2, 0);

    out_kernel<<<M1, 256>>>(out);

    cudaEventDestroy(evFork);
    cudaEventDestroy(evJ1);
    cudaEventDestroy(evJ2);
    cudaStreamDestroy(s1);
    cudaStreamDestroy(s2);
}

// round 15
// speedup vs baseline: 1.1834x; 1.1834x over previous
#include <cuda_runtime.h>
#include <cstdint>

// Problem constants
#define BB 4
#define N1 8192
#define N2 2048
#define INP 512
#define OUTP 256
#define M1 (BB * N1)   // 32768
#define M2 (BB * N2)   // 8192

// Device scratch
__device__ float g_y1[M1 * OUTP];     // x1@W1+b1  (32 MB)
__device__ float g_y2[M2 * OUTP];     // x2@W2+b2  (8 MB)
__device__ float g_Wt1[OUTP * OUTP];  // W1^T  [N,K]
__device__ float g_Wt2[OUTP * INP];   // W2^T  [N,K]
__device__ float g_stats1[2 * OUTP];
__device__ float g_stats2[2 * OUTP];
__device__ int   g_idx[BB * N1 * 3];
__device__ float g_w[BB * N1 * 3];

// smem row stride for tf32 tiles: 36 words = 144 bytes.
#define SW 36
#define STAGE_BYTES (2 * 128 * SW * 4)      // A + B per stage = 36864
#define B_OFF_BYTES (128 * SW * 4)          // 18432
#define GEMM_SMEM   (2 * STAGE_BYTES)       // 73728

// ---------------------------------------------------------------------------
__device__ __forceinline__ uint32_t smem_u32(const void* p) {
    uint32_t a;
    asm("{ .reg .u64 t; cvta.to.shared.u64 t, %1; cvt.u32.u64 %0, t; }"
        : "=r"(a) : "l"(p));
    return a;
}

__device__ __forceinline__ void ldmx4(uint32_t addr, uint32_t* r) {
    asm volatile("ldmatrix.sync.aligned.m8n8.x4.shared.b16 {%0,%1,%2,%3}, [%4];"
                 : "=r"(r[0]), "=r"(r[1]), "=r"(r[2]), "=r"(r[3]) : "r"(addr));
}

// m16n8k8 tf32 MMA, fp32 accumulate
__device__ __forceinline__ void mma_tf32(float* c, const uint32_t* a,
                                         const uint32_t* b) {
    asm volatile(
        "mma.sync.aligned.m16n8k8.row.col.f32.tf32.tf32.f32 "
        "{%0,%1,%2,%3}, {%4,%5,%6,%7}, {%8,%9}, {%0,%1,%2,%3};"
        : "+f"(c[0]), "+f"(c[1]), "+f"(c[2]), "+f"(c[3])
        : "r"(a[0]), "r"(a[1]), "r"(a[2]), "r"(a[3]), "r"(b[0]), "r"(b[1]));
}

__device__ __forceinline__ void cpasync16(uint32_t d, const void* s) {
    asm volatile("cp.async.cg.shared.global [%0], [%1], 16;"
                 :: "r"(d), "l"(s) : "memory");
}
#define CP_COMMIT() asm volatile("cp.async.commit_group;" ::: "memory")
#define CP_WAIT1()  asm volatile("cp.async.wait_group 1;" ::: "memory")

// ---------------------------------------------------------------------------
__global__ void zero_stats_kernel() {
    int t = threadIdx.x;
    if (t < 2 * OUTP) { g_stats1[t] = 0.f; g_stats2[t] = 0.f; }
}

// Tiled transpose: dst[C][R] = src[R][C]^T. block (32,8), grid (C/32, R/32)
__global__ __launch_bounds__(256) void transpose_kernel(
    const float* __restrict__ src, float* __restrict__ dst, int R, int C)
{
    __shared__ float t[32][33];
    int bx = blockIdx.x * 32, by = blockIdx.y * 32;
    int x = bx + threadIdx.x;
    #pragma unroll
    for (int i = 0; i < 32; i += 8)
        t[threadIdx.y + i][threadIdx.x] = src[(size_t)(by + threadIdx.y + i) * C + x];
    __syncthreads();
    int x2 = by + threadIdx.x;
    #pragma unroll
    for (int i = 0; i < 32; i += 8)
        dst[(size_t)(bx + threadIdx.y + i) * R + x2] = t[threadIdx.x][threadIdx.y + i];
}

// ---------------------------------------------------------------------------
// TF32 HMMA GEMM, cp.async double-buffered (R12 winner, unchanged).
template<int K>
__global__ __launch_bounds__(256) void gemm_tf32_pipe_kernel(
    const float* __restrict__ A, const float* __restrict__ Wt,
    const float* __restrict__ bias, float* __restrict__ C)
{
    extern __shared__ uint32_t smem[];
    const uint32_t base_u = smem_u32(smem);
    constexpr int NCH = K / 32;

    const int tid = threadIdx.x;
    const int wid = tid >> 5;
    const int lane = tid & 31;
    const int gid = lane >> 2;
    const int tig = lane & 3;

    const int rowBase = blockIdx.y * 128;
    const int colBase = blockIdx.x * 128;
    const int m0 = (wid & 1) * 64;
    const int n0 = (wid >> 1) * 32;

    const int lrow = ((lane >> 3) & 1) * 8 + (lane & 7);
    const int lc16 = (lane >> 4) * 16;
    const uint32_t aLane = (uint32_t)(m0 + lrow) * 144 + lc16;
    const uint32_t bLane = (uint32_t)(n0 + lrow) * 144 + lc16 + B_OFF_BYTES;

    const int ldRow = tid >> 3;
    const int ldC = tid & 7;

    float acc[4][4][4];
    #pragma unroll
    for (int mt = 0; mt < 4; mt++)
        #pragma unroll
        for (int nt = 0; nt < 4; nt++)
            #pragma unroll
            for (int e = 0; e < 4; e++) acc[mt][nt][e] = 0.f;

    auto issue_stage = [&](int slot, int k0) {
        const uint32_t st = base_u + slot * STAGE_BYTES;
        #pragma unroll
        for (int l = 0; l < 4; l++) {
            int r = ldRow + l * 32;
            uint32_t d = st + (uint32_t)r * 144 + ldC * 16;
            cpasync16(d, A + (size_t)(rowBase + r) * K + k0 + ldC * 4);
            cpasync16(d + B_OFF_BYTES, Wt + (size_t)(colBase + r) * K + k0 + ldC * 4);
        }
        CP_COMMIT();
    };

    issue_stage(0, 0);
    issue_stage(1, 32);

    for (int c = 0; c < NCH; c++) {
        CP_WAIT1();
        __syncthreads();
        const uint32_t st = base_u + (c & 1) * STAGE_BYTES;
        const uint32_t aBase = st + aLane;
        const uint32_t bBase = st + bLane;

        #pragma unroll
        for (int kt = 0; kt < 4; kt++) {
            uint32_t b[4][2];
            #pragma unroll
            for (int np = 0; np < 2; np++) {
                uint32_t r4[4];
                ldmx4(bBase + np * (16 * 144) + kt * 32, r4);
                b[np * 2][0]     = r4[0];
                b[np * 2 + 1][0] = r4[1];
                b[np * 2][1]     = r4[2];
                b[np * 2 + 1][1] = r4[3];
            }
            #pragma unroll
            for (int mt = 0; mt < 4; mt++) {
                uint32_t a[4];
                ldmx4(aBase + mt * (16 * 144) + kt * 32, a);
                #pragma unroll
                for (int nt = 0; nt < 4; nt++)
                    mma_tf32(acc[mt][nt], a, b[nt]);
            }
        }
        __syncthreads();
        if (c + 2 < NCH) issue_stage(c & 1, (c + 2) * 32);
        else CP_COMMIT();
    }

    #pragma unroll
    for (int nt = 0; nt < 4; nt++) {
        const int cg = colBase + n0 + nt * 8 + tig * 2;
        float2 bv = *(const float2*)(bias + cg);
        #pragma unroll
        for (int mt = 0; mt < 4; mt++) {
            int rg0 = rowBase + m0 + mt * 16 + gid;
            float2 v0 = make_float2(acc[mt][nt][0] + bv.x, acc[mt][nt][1] + bv.y);
            float2 v1 = make_float2(acc[mt][nt][2] + bv.x, acc[mt][nt][3] + bv.y);
            *(float2*)(C + (size_t)rg0 * OUTP + cg) = v0;
            *(float2*)(C + (size_t)(rg0 + 8) * OUTP + cg) = v1;
        }
    }
}

// ---------------------------------------------------------------------------
__global__ __launch_bounds__(256) void stats_kernel(
    const float* __restrict__ y, int rows, float* __restrict__ stats)
{
    int c = threadIdx.x;
    float s = 0.f, q = 0.f;
    for (int r = blockIdx.x; r < rows; r += gridDim.x) {
        float v = y[(size_t)r * OUTP + c];
        s += v;
        q = fmaf(v, v, q);
    }
    atomicAdd(&stats[c], s);
    atomicAdd(&stats[OUTP + c], q);
}

// ---------------------------------------------------------------------------
// 3-NN (proven scan), 256 blocks x 128 threads for full-SM coverage.
__global__ __launch_bounds__(128) void knn_kernel(
    const float* __restrict__ p1, const float* __restrict__ p2)
{
    __shared__ float4 sp[N2];
    const int b     = blockIdx.x >> 6;    // 64 chunks of 128 per batch
    const int chunk = blockIdx.x & 63;

    const float* P2 = p2 + (size_t)b * N2 * 3;
    for (int i = threadIdx.x; i < N2; i += 128) {
        float x = P2[i * 3 + 0], y = P2[i * 3 + 1], z = P2[i * 3 + 2];
        sp[i] = make_float4(x, y, z, fmaf(x, x, fmaf(y, y, z * z)));
    }
    __syncthreads();

    const int n = chunk * 128 + threadIdx.x;
    const float* P1 = p1 + ((size_t)b * N1 + n) * 3;
    const float px = P1[0], py = P1[1], pz = P1[2];
    const float s1 = fmaf(px, px, fmaf(py, py, pz * pz));

    float d0 = 1e30f, d1 = 1e30f, d2 = 1e30f;
    int   i0 = 0,     i1 = 0,     i2 = 0;

    #pragma unroll 4
    for (int j = 0; j < N2; j++) {
        float4 qq = sp[j];
        float dot = fmaf(px, qq.x, fmaf(py, qq.y, pz * qq.z));
        float d = (s1 + qq.w) - 2.f * dot;
        if (d < d2) {
            if (d < d1) {
                d2 = d1; i2 = i1;
                if (d < d0) { d1 = d0; i1 = i0; d0 = d; i0 = j; }
                else        { d1 = d;  i1 = j; }
            } else { d2 = d; i2 = j; }
        }
    }

    float r0 = 1.f / (d0 + 1e-8f);
    float r1 = 1.f / (d1 + 1e-8f);
    float r2 = 1.f / (d2 + 1e-8f);
    float rs = 1.f / (r0 + r1 + r2);

    size_t o = ((size_t)b * N1 + n) * 3;
    g_idx[o + 0] = b * N2 + i0;
    g_idx[o + 1] = b * N2 + i1;
    g_idx[o + 2] = b * N2 + i2;
    g_w[o + 0] = r0 * rs;
    g_w[o + 1] = r1 * rs;
    g_w[o + 2] = r2 * rs;
}

// ---------------------------------------------------------------------------
// Output kernel with fused BN finalize: scale/shift computed from raw stats.
__global__ __launch_bounds__(256) void out_kernel(
    float* __restrict__ out,
    const float* __restrict__ gamma1, const float* __restrict__ beta1,
    const float* __restrict__ gamma2, const float* __restrict__ beta2)
{
    const int r = blockIdx.x;
    const int c = threadIdx.x;

    // finalize BN1 for channel c
    const float inv1 = 1.f / (float)M1;
    float mean1 = g_stats1[c] * inv1;
    float var1  = g_stats1[OUTP + c] * inv1 - mean1 * mean1;
    float a1 = gamma1[c] * rsqrtf(var1 + 1e-5f);
    float s1 = beta1[c] - mean1 * a1;

    // finalize BN2 for channel c
    const float inv2 = 1.f / (float)M2;
    float mean2 = g_stats2[c] * inv2;
    float var2  = g_stats2[OUTP + c] * inv2 - mean2 * mean2;
    float a2 = gamma2[c] * rsqrtf(var2 + 1e-5f);
    float s2 = beta2[c] - mean2 * a2;

    const size_t o3 = (size_t)r * 3;
    const int   j0 = g_idx[o3 + 0], j1 = g_idx[o3 + 1], j2 = g_idx[o3 + 2];
    const float w0 = g_w[o3 + 0],   w1 = g_w[o3 + 1],   w2 = g_w[o3 + 2];

    float v1 = fmaxf(fmaf(g_y1[(size_t)r * OUTP + c], a1, s1), 0.f);
    float h0 = fmaxf(fmaf(g_y2[(size_t)j0 * OUTP + c], a2, s2), 0.f);
    float h1 = fmaxf(fmaf(g_y2[(size_t)j1 * OUTP + c], a2, s2), 0.f);
    float h2 = fmaxf(fmaf(g_y2[(size_t)j2 * OUTP + c], a2, s2), 0.f);

    out[(size_t)r * OUTP + c] = v1 + fmaf(w0, h0, fmaf(w1, h1, w2 * h2));
}

// ---------------------------------------------------------------------------
extern "C" void kernel_launch(void* const* d_in, const int* in_sizes, int n_in,
                              void* d_out, int out_size)
{
    const float* p1     = (const float*)d_in[0];
    const float* x1     = (const float*)d_in[1];
    const float* p2     = (const float*)d_in[2];
    const float* x2     = (const float*)d_in[3];
    const float* W1     = (const float*)d_in[4];
    const float* b1     = (const float*)d_in[5];
    const float* gamma1 = (const float*)d_in[6];
    const float* beta1  = (const float*)d_in[7];
    const float* W2     = (const float*)d_in[8];
    const float* b2     = (const float*)d_in[9];
    const float* gamma2 = (const float*)d_in[10];
    const float* beta2  = (const float*)d_in[11];
    float* out = (float*)d_out;

    float *y1, *y2, *st1, *st2, *wt1, *wt2;
    cudaGetSymbolAddress((void**)&y1,  g_y1);
    cudaGetSymbolAddress((void**)&y2,  g_y2);
    cudaGetSymbolAddress((void**)&st1, g_stats1);
    cudaGetSymbolAddress((void**)&st2, g_stats2);
    cudaGetSymbolAddress((void**)&wt1, g_Wt1);
    cudaGetSymbolAddress((void**)&wt2, g_Wt2);

    cudaFuncSetAttribute(gemm_tf32_pipe_kernel<INP>,
                         cudaFuncAttributeMaxDynamicSharedMemorySize, GEMM_SMEM);
    cudaFuncSetAttribute(gemm_tf32_pipe_kernel<OUTP>,
                         cudaFuncAttributeMaxDynamicSharedMemorySize, GEMM_SMEM);

    zero_stats_kernel<<<1, 512>>>();

    // Transpose weights into [N,K]
    transpose_kernel<<<dim3(OUTP / 32, INP / 32), dim3(32, 8)>>>(W2, wt2, INP, OUTP);
    transpose_kernel<<<dim3(OUTP / 32, OUTP / 32), dim3(32, 8)>>>(W1, wt1, OUTP, OUTP);

    // cp.async-pipelined TF32 GEMMs
    gemm_tf32_pipe_kernel<INP><<<dim3(2, M2 / 128), 256, GEMM_SMEM>>>(x2, wt2, b2, y2);
    gemm_tf32_pipe_kernel<OUTP><<<dim3(2, M1 / 128), 256, GEMM_SMEM>>>(x1, wt1, b1, y1);

    stats_kernel<<<1024, 256>>>(y2, M2, st2);
    stats_kernel<<<2048, 256>>>(y1, M1, st1);

    knn_kernel<<<BB * (N1 / 128), 128>>>(p1, p2);

    out_kernel<<<M1, 256>>>(out, gamma1, beta1, gamma2, beta2);
}

// round 16
// speedup vs baseline: 1.2633x; 1.0675x over previous
#include <cuda_runtime.h>
#include <cstdint>

// Problem constants
#define BB 4
#define N1 8192
#define N2 2048
#define INP 512
#define OUTP 256
#define M1 (BB * N1)   // 32768
#define M2 (BB * N2)   // 8192

// Device scratch
__device__ float g_y1[M1 * OUTP];     // x1@W1+b1  (32 MB)
__device__ float g_y2[M2 * OUTP];     // x2@W2+b2  (8 MB)
__device__ float g_Wt1[OUTP * OUTP];  // W1^T  [N,K]
__device__ float g_Wt2[OUTP * INP];   // W2^T  [N,K]
__device__ float g_stats1[2 * OUTP];
__device__ float g_stats2[2 * OUTP];
__device__ float g_ab1[2 * OUTP];
__device__ float g_ab2[2 * OUTP];
__device__ int   g_idx[BB * N1 * 3];
__device__ float g_w[BB * N1 * 3];

// smem row stride for tf32 tiles: 36 words = 144 bytes.
#define SW 36
#define STAGE_BYTES (2 * 128 * SW * 4)      // A + B per stage = 36864
#define B_OFF_BYTES (128 * SW * 4)          // 18432
#define GEMM_SMEM   (2 * STAGE_BYTES)       // 73728

// ---------------------------------------------------------------------------
__device__ __forceinline__ uint32_t smem_u32(const void* p) {
    uint32_t a;
    asm("{ .reg .u64 t; cvta.to.shared.u64 t, %1; cvt.u32.u64 %0, t; }"
        : "=r"(a) : "l"(p));
    return a;
}

__device__ __forceinline__ void ldmx4(uint32_t addr, uint32_t* r) {
    asm volatile("ldmatrix.sync.aligned.m8n8.x4.shared.b16 {%0,%1,%2,%3}, [%4];"
                 : "=r"(r[0]), "=r"(r[1]), "=r"(r[2]), "=r"(r[3]) : "r"(addr));
}

// m16n8k8 tf32 MMA, fp32 accumulate
__device__ __forceinline__ void mma_tf32(float* c, const uint32_t* a,
                                         const uint32_t* b) {
    asm volatile(
        "mma.sync.aligned.m16n8k8.row.col.f32.tf32.tf32.f32 "
        "{%0,%1,%2,%3}, {%4,%5,%6,%7}, {%8,%9}, {%0,%1,%2,%3};"
        : "+f"(c[0]), "+f"(c[1]), "+f"(c[2]), "+f"(c[3])
        : "r"(a[0]), "r"(a[1]), "r"(a[2]), "r"(a[3]), "r"(b[0]), "r"(b[1]));
}

__device__ __forceinline__ void cpasync16(uint32_t d, const void* s) {
    asm volatile("cp.async.cg.shared.global [%0], [%1], 16;"
                 :: "r"(d), "l"(s) : "memory");
}
#define CP_COMMIT() asm volatile("cp.async.commit_group;" ::: "memory")
#define CP_WAIT1()  asm volatile("cp.async.wait_group 1;" ::: "memory")

// ---------------------------------------------------------------------------
__global__ void zero_stats_kernel() {
    int t = threadIdx.x;
    if (t < 2 * OUTP) { g_stats1[t] = 0.f; g_stats2[t] = 0.f; }
}

// Tiled transpose: dst[C][R] = src[R][C]^T. block (32,8), grid (C/32, R/32)
__global__ __launch_bounds__(256) void transpose_kernel(
    const float* __restrict__ src, float* __restrict__ dst, int R, int C)
{
    __shared__ float t[32][33];
    int bx = blockIdx.x * 32, by = blockIdx.y * 32;
    int x = bx + threadIdx.x;
    #pragma unroll
    for (int i = 0; i < 32; i += 8)
        t[threadIdx.y + i][threadIdx.x] = src[(size_t)(by + threadIdx.y + i) * C + x];
    __syncthreads();
    int x2 = by + threadIdx.x;
    #pragma unroll
    for (int i = 0; i < 32; i += 8)
        dst[(size_t)(bx + threadIdx.y + i) * R + x2] = t[threadIdx.x][threadIdx.y + i];
}

// ---------------------------------------------------------------------------
// TF32 HMMA GEMM, cp.async double-buffered (R12 winner, unchanged).
template<int K>
__global__ __launch_bounds__(256) void gemm_tf32_pipe_kernel(
    const float* __restrict__ A, const float* __restrict__ Wt,
    const float* __restrict__ bias, float* __restrict__ C)
{
    extern __shared__ uint32_t smem[];
    const uint32_t base_u = smem_u32(smem);
    constexpr int NCH = K / 32;

    const int tid = threadIdx.x;
    const int wid = tid >> 5;
    const int lane = tid & 31;
    const int gid = lane >> 2;
    const int tig = lane & 3;

    const int rowBase = blockIdx.y * 128;
    const int colBase = blockIdx.x * 128;
    const int m0 = (wid & 1) * 64;
    const int n0 = (wid >> 1) * 32;

    const int lrow = ((lane >> 3) & 1) * 8 + (lane & 7);
    const int lc16 = (lane >> 4) * 16;
    const uint32_t aLane = (uint32_t)(m0 + lrow) * 144 + lc16;
    const uint32_t bLane = (uint32_t)(n0 + lrow) * 144 + lc16 + B_OFF_BYTES;

    const int ldRow = tid >> 3;
    const int ldC = tid & 7;

    float acc[4][4][4];
    #pragma unroll
    for (int mt = 0; mt < 4; mt++)
        #pragma unroll
        for (int nt = 0; nt < 4; nt++)
            #pragma unroll
            for (int e = 0; e < 4; e++) acc[mt][nt][e] = 0.f;

    auto issue_stage = [&](int slot, int k0) {
        const uint32_t st = base_u + slot * STAGE_BYTES;
        #pragma unroll
        for (int l = 0; l < 4; l++) {
            int r = ldRow + l * 32;
            uint32_t d = st + (uint32_t)r * 144 + ldC * 16;
            cpasync16(d, A + (size_t)(rowBase + r) * K + k0 + ldC * 4);
            cpasync16(d + B_OFF_BYTES, Wt + (size_t)(colBase + r) * K + k0 + ldC * 4);
        }
        CP_COMMIT();
    };

    issue_stage(0, 0);
    issue_stage(1, 32);

    for (int c = 0; c < NCH; c++) {
        CP_WAIT1();
        __syncthreads();
        const uint32_t st = base_u + (c & 1) * STAGE_BYTES;
        const uint32_t aBase = st + aLane;
        const uint32_t bBase = st + bLane;

        #pragma unroll
        for (int kt = 0; kt < 4; kt++) {
            uint32_t b[4][2];
            #pragma unroll
            for (int np = 0; np < 2; np++) {
                uint32_t r4[4];
                ldmx4(bBase + np * (16 * 144) + kt * 32, r4);
                b[np * 2][0]     = r4[0];
                b[np * 2 + 1][0] = r4[1];
                b[np * 2][1]     = r4[2];
                b[np * 2 + 1][1] = r4[3];
            }
            #pragma unroll
            for (int mt = 0; mt < 4; mt++) {
                uint32_t a[4];
                ldmx4(aBase + mt * (16 * 144) + kt * 32, a);
                #pragma unroll
                for (int nt = 0; nt < 4; nt++)
                    mma_tf32(acc[mt][nt], a, b[nt]);
            }
        }
        __syncthreads();
        if (c + 2 < NCH) issue_stage(c & 1, (c + 2) * 32);
        else CP_COMMIT();
    }

    #pragma unroll
    for (int nt = 0; nt < 4; nt++) {
        const int cg = colBase + n0 + nt * 8 + tig * 2;
        float2 bv = *(const float2*)(bias + cg);
        #pragma unroll
        for (int mt = 0; mt < 4; mt++) {
            int rg0 = rowBase + m0 + mt * 16 + gid;
            float2 v0 = make_float2(acc[mt][nt][0] + bv.x, acc[mt][nt][1] + bv.y);
            float2 v1 = make_float2(acc[mt][nt][2] + bv.x, acc[mt][nt][3] + bv.y);
            *(float2*)(C + (size_t)rg0 * OUTP + cg) = v0;
            *(float2*)(C + (size_t)(rg0 + 8) * OUTP + cg) = v1;
        }
    }
}

// ---------------------------------------------------------------------------
__global__ __launch_bounds__(256) void stats_kernel(
    const float* __restrict__ y, int rows, float* __restrict__ stats)
{
    int c = threadIdx.x;
    float s = 0.f, q = 0.f;
    for (int r = blockIdx.x; r < rows; r += gridDim.x) {
        float v = y[(size_t)r * OUTP + c];
        s += v;
        q = fmaf(v, v, q);
    }
    atomicAdd(&stats[c], s);
    atomicAdd(&stats[OUTP + c], q);
}

__global__ void finalize_kernel(const float* __restrict__ stats,
                                const float* __restrict__ gamma,
                                const float* __restrict__ beta,
                                float inv_count, float* __restrict__ ab)
{
    int c = threadIdx.x;
    float mean = stats[c] * inv_count;
    float var  = stats[OUTP + c] * inv_count - mean * mean;
    float scale = gamma[c] * rsqrtf(var + 1e-5f);
    ab[c]        = scale;
    ab[OUTP + c] = beta[c] - mean * scale;
}

// ---------------------------------------------------------------------------
// 3-NN (proven scan, R12 config)
__global__ __launch_bounds__(256) void knn_kernel(
    const float* __restrict__ p1, const float* __restrict__ p2)
{
    __shared__ float4 sp[N2];
    const int b     = blockIdx.x >> 5;
    const int chunk = blockIdx.x & 31;

    const float* P2 = p2 + (size_t)b * N2 * 3;
    for (int i = threadIdx.x; i < N2; i += 256) {
        float x = P2[i * 3 + 0], y = P2[i * 3 + 1], z = P2[i * 3 + 2];
        sp[i] = make_float4(x, y, z, fmaf(x, x, fmaf(y, y, z * z)));
    }
    __syncthreads();

    const int n = chunk * 256 + threadIdx.x;
    const float* P1 = p1 + ((size_t)b * N1 + n) * 3;
    const float px = P1[0], py = P1[1], pz = P1[2];
    const float s1 = fmaf(px, px, fmaf(py, py, pz * pz));

    float d0 = 1e30f, d1 = 1e30f, d2 = 1e30f;
    int   i0 = 0,     i1 = 0,     i2 = 0;

    #pragma unroll 4
    for (int j = 0; j < N2; j++) {
        float4 qq = sp[j];
        float dot = fmaf(px, qq.x, fmaf(py, qq.y, pz * qq.z));
        float d = (s1 + qq.w) - 2.f * dot;
        if (d < d2) {
            if (d < d1) {
                d2 = d1; i2 = i1;
                if (d < d0) { d1 = d0; i1 = i0; d0 = d; i0 = j; }
                else        { d1 = d;  i1 = j; }
            } else { d2 = d; i2 = j; }
        }
    }

    float r0 = 1.f / (d0 + 1e-8f);
    float r1 = 1.f / (d1 + 1e-8f);
    float r2 = 1.f / (d2 + 1e-8f);
    float rs = 1.f / (r0 + r1 + r2);

    size_t o = ((size_t)b * N1 + n) * 3;
    g_idx[o + 0] = b * N2 + i0;
    g_idx[o + 1] = b * N2 + i1;
    g_idx[o + 2] = b * N2 + i2;
    g_w[o + 0] = r0 * rs;
    g_w[o + 1] = r1 * rs;
    g_w[o + 2] = r2 * rs;
}

// ---------------------------------------------------------------------------
// Output kernel, grid-strided: 2048 blocks, 16 rows each; ab loads hoisted.
#define OUT_BLOCKS 2048

__global__ __launch_bounds__(256) void out_kernel(float* __restrict__ out)
{
    const int c = threadIdx.x;

    // per-channel BN params loaded ONCE per block (registers across row loop)
    const float a1 = g_ab1[c], s1 = g_ab1[OUTP + c];
    const float a2 = g_ab2[c], s2 = g_ab2[OUTP + c];

    for (int r = blockIdx.x; r < M1; r += OUT_BLOCKS) {
        const size_t o3 = (size_t)r * 3;
        const int   j0 = g_idx[o3 + 0], j1 = g_idx[o3 + 1], j2 = g_idx[o3 + 2];
        const float w0 = g_w[o3 + 0],   w1 = g_w[o3 + 1],   w2 = g_w[o3 + 2];

        float v1 = fmaxf(fmaf(g_y1[(size_t)r * OUTP + c], a1, s1), 0.f);
        float h0 = fmaxf(fmaf(g_y2[(size_t)j0 * OUTP + c], a2, s2), 0.f);
        float h1 = fmaxf(fmaf(g_y2[(size_t)j1 * OUTP + c], a2, s2), 0.f);
        float h2 = fmaxf(fmaf(g_y2[(size_t)j2 * OUTP + c], a2, s2), 0.f);

        out[(size_t)r * OUTP + c] = v1 + fmaf(w0, h0, fmaf(w1, h1, w2 * h2));
    }
}

// ---------------------------------------------------------------------------
extern "C" void kernel_launch(void* const* d_in, const int* in_sizes, int n_in,
                              void* d_out, int out_size)
{
    const float* p1     = (const float*)d_in[0];
    const float* x1     = (const float*)d_in[1];
    const float* p2     = (const float*)d_in[2];
    const float* x2     = (const float*)d_in[3];
    const float* W1     = (const float*)d_in[4];
    const float* b1     = (const float*)d_in[5];
    const float* gamma1 = (const float*)d_in[6];
    const float* beta1  = (const float*)d_in[7];
    const float* W2     = (const float*)d_in[8];
    const float* b2     = (const float*)d_in[9];
    const float* gamma2 = (const float*)d_in[10];
    const float* beta2  = (const float*)d_in[11];
    float* out = (float*)d_out;

    float *y1, *y2, *st1, *st2, *ab1, *ab2, *wt1, *wt2;
    cudaGetSymbolAddress((void**)&y1,  g_y1);
    cudaGetSymbolAddress((void**)&y2,  g_y2);
    cudaGetSymbolAddress((void**)&st1, g_stats1);
    cudaGetSymbolAddress((void**)&st2, g_stats2);
    cudaGetSymbolAddress((void**)&ab1, g_ab1);
    cudaGetSymbolAddress((void**)&ab2, g_ab2);
    cudaGetSymbolAddress((void**)&wt1, g_Wt1);
    cudaGetSymbolAddress((void**)&wt2, g_Wt2);

    cudaFuncSetAttribute(gemm_tf32_pipe_kernel<INP>,
                         cudaFuncAttributeMaxDynamicSharedMemorySize, GEMM_SMEM);
    cudaFuncSetAttribute(gemm_tf32_pipe_kernel<OUTP>,
                         cudaFuncAttributeMaxDynamicSharedMemorySize, GEMM_SMEM);

    zero_stats_kernel<<<1, 512>>>();

    // Transpose weights into [N,K]
    transpose_kernel<<<dim3(OUTP / 32, INP / 32), dim3(32, 8)>>>(W2, wt2, INP, OUTP);
    transpose_kernel<<<dim3(OUTP / 32, OUTP / 32), dim3(32, 8)>>>(W1, wt1, OUTP, OUTP);

    // cp.async-pipelined TF32 GEMMs
    gemm_tf32_pipe_kernel<INP><<<dim3(2, M2 / 128), 256, GEMM_SMEM>>>(x2, wt2, b2, y2);
    gemm_tf32_pipe_kernel<OUTP><<<dim3(2, M1 / 128), 256, GEMM_SMEM>>>(x1, wt1, b1, y1);

    stats_kernel<<<512, 256>>>(y2, M2, st2);
    stats_kernel<<<2048, 256>>>(y1, M1, st1);

    finalize_kernel<<<1, 256>>>(st2, gamma2, beta2, 1.f / (float)M2, ab2);
    finalize_kernel<<<1, 256>>>(st1, gamma1, beta1, 1.f / (float)M1, ab1);

    knn_kernel<<<BB * (N1 / 256), 256>>>(p1, p2);

    out_kernel<<<OUT_BLOCKS, 256>>>(out);
}